// round 10
// baseline (speedup 1.0000x reference)
#include <cuda_runtime.h>
#include <cuda_bf16.h>
#include <cstdint>

#define NROWS_MAX 65536
typedef unsigned long long ull;

// scratch: left/right activations [n][0..31]=left, [n][32..63]=right
__device__ __align__(16) float g_lr[(size_t)NROWS_MAX * 64];
// pre-split Ws1, bf16, N-major, XOR-swizzled: [17 chunks][128 n][64 k]
__device__ __align__(16) __nv_bfloat16 g_whi[17 * 8192];
__device__ __align__(16) __nv_bfloat16 g_wlo[17 * 8192];

// ---------- packed f32x2 helpers (k_lr) ----------
__device__ __forceinline__ ull pk2(float x) {
    ull r; asm("mov.b64 %0, {%1, %1};" : "=l"(r) : "f"(x)); return r;
}
__device__ __forceinline__ void fma2(ull &d, ull a, ull b) {
    asm("fma.rn.f32x2 %0, %1, %2, %0;" : "+l"(d) : "l"(a), "l"(b));
}
__device__ __forceinline__ ull mul2(ull a, ull b) {
    ull d; asm("mul.rn.f32x2 %0, %1, %2;" : "=l"(d) : "l"(a), "l"(b)); return d;
}
__device__ __forceinline__ float2 up2(ull v) {
    float2 f; asm("mov.b64 {%0, %1}, %2;" : "=f"(f.x), "=f"(f.y) : "l"(v)); return f;
}
// ---------- cp.async ----------
__device__ __forceinline__ uint32_t s2u(const void* p) {
    uint32_t a;
    asm("{ .reg .u64 t; cvta.to.shared.u64 t, %1; cvt.u32.u64 %0, t; }" : "=r"(a) : "l"(p));
    return a;
}
__device__ __forceinline__ void cpa16(uint32_t dst, const void* src) {
    asm volatile("cp.async.ca.shared.global [%0], [%1], 16;" :: "r"(dst), "l"(src));
}
__device__ __forceinline__ void cpa_commit() { asm volatile("cp.async.commit_group;"); }
template<int N> __device__ __forceinline__ void cpa_wait() {
    asm volatile("cp.async.wait_group %0;" :: "n"(N));
}
// ---------- tensor primitives ----------
__device__ __forceinline__ void ldsm4(uint32_t* r, uint32_t a) {
    asm volatile("ldmatrix.sync.aligned.m8n8.x4.shared.b16 {%0,%1,%2,%3}, [%4];"
        : "=r"(r[0]), "=r"(r[1]), "=r"(r[2]), "=r"(r[3]) : "r"(a));
}
__device__ __forceinline__ void mma_bf16(float* d, const uint32_t* a, const uint32_t* b) {
    asm volatile("mma.sync.aligned.m16n8k16.row.col.f32.bf16.bf16.f32 "
        "{%0,%1,%2,%3}, {%4,%5,%6,%7}, {%8,%9}, {%0,%1,%2,%3};"
        : "+f"(d[0]), "+f"(d[1]), "+f"(d[2]), "+f"(d[3])
        : "r"(a[0]), "r"(a[1]), "r"(a[2]), "r"(a[3]), "r"(b[0]), "r"(b[1]));
}

// =====================================================================
// Kernel 0: split Ws1 [1088][128] -> bf16 hi/lo, N-major swizzled
// =====================================================================
__global__ void k_conv(const float* __restrict__ Ws1) {
    int gid = blockIdx.x * 256 + threadIdx.x;
    if (gid >= 17 * 64 * 128) return;
    int s = gid >> 13, rem = gid & 8191;
    int k = rem >> 7, n = rem & 127;
    float w = Ws1[(s * 64 + k) * 128 + n];
    __nv_bfloat16 hi = __float2bfloat16(w);
    __nv_bfloat16 lo = __float2bfloat16(w - __bfloat162float(hi));
    uint32_t off = (uint32_t)s * 16384 + n * 128 + ((((k >> 3) ^ (n & 7))) << 4) + (k & 7) * 2;
    *(__nv_bfloat16*)((char*)g_whi + off) = hi;
    *(__nv_bfloat16*)((char*)g_wlo + off) = lo;
}

// =====================================================================
// Kernel A: left/right = im(..) @ Wa + ba  (proven FFMA2 path, unchanged)
// =====================================================================
#define PADA 132
__global__ __launch_bounds__(128, 4) void k_lr(
    const float* __restrict__ concepts, const float* __restrict__ Wn,
    const float* __restrict__ bn, const float* __restrict__ Wa,
    const float* __restrict__ ba, const void* __restrict__ idxp,
    int nrows)
{
    __shared__ __align__(16) float uT[32 * PADA];
    __shared__ __align__(16) float vT[32 * PADA];
    __shared__ __align__(16) float Bs[3 * 1024];

    int tid  = threadIdx.x;
    int lane = tid & 31, w = tid >> 5;
    int nb128 = nrows >> 7;
    bool leftside = (blockIdx.x < (unsigned)nb128);
    int n0 = (leftside ? blockIdx.x : blockIdx.x - nb128) << 7;
    int cu_col = leftside ? 0 : 2;

    uint32_t bs_base = s2u(Bs);
    int e0 = tid * 2;
    #pragma unroll
    for (int p = 0; p < 2; ++p) {
        #pragma unroll
        for (int q = 0; q < 2; ++q)
            cpa16(bs_base + ((p % 3) * 1024 + (e0 + q) * 4) * 4,
                  Wa + (size_t)p * 1024 + (e0 + q) * 4);
        cpa_commit();
    }

    const int* idx32 = (const int*)idxp;
    bool is64 = (idx32[1] == 0) & (idx32[3] == 0) & (idx32[5] == 0) & (idx32[7] == 0);
    const long long* idx64 = (const long long*)idxp;

    for (int it = 0; it < 32; ++it) {
        int r = it * 4 + w;
        long long base = (long long)(n0 + r) * 4 + cu_col;
        long long cu = is64 ? idx64[base]     : (long long)idx32[base];
        long long cv = is64 ? idx64[base + 1] : (long long)idx32[base + 1];
        uT[lane * PADA + r] = concepts[cu * 32 + lane];
        vT[lane * PADA + r] = concepts[cv * 32 + lane];
    }
    __syncthreads();

    if (leftside) {
        float wn[32];
        #pragma unroll
        for (int i2 = 0; i2 < 32; ++i2) wn[i2] = Wn[i2 * 32 + lane];
        float bnk = bn[lane];
        for (int rr = 0; rr < 32; ++rr) {
            int r = (w << 5) + rr;
            float na = bnk;
            #pragma unroll
            for (int i2 = 0; i2 < 32; ++i2)
                na = fmaf(uT[i2 * PADA + r], wn[i2], na);
            __syncwarp();
            uT[lane * PADA + r] = na;
            __syncwarp();
        }
    }
    __syncthreads();

    int tc = tid & 7, tr = tid >> 3;
    int c0 = tc << 2, r0 = tr << 3;
    ull acc[4][4];
    #pragma unroll
    for (int p = 0; p < 4; ++p)
        #pragma unroll
        for (int c = 0; c < 4; ++c) acc[p][c] = 0ull;

    for (int s = 0; s < 34; ++s) {
        cpa_wait<1>();
        __syncthreads();
        if (s + 2 < 34) {
            #pragma unroll
            for (int q = 0; q < 2; ++q)
                cpa16(bs_base + (((s + 2) % 3) * 1024 + (e0 + q) * 4) * 4,
                      Wa + (size_t)(s + 2) * 1024 + (e0 + q) * 4);
        }
        cpa_commit();

        const float* Bc = Bs + (s % 3) * 1024;

        if (s >= 2) {
            int ii = s - 2;
            ull qa[4][4];
            #pragma unroll
            for (int kk = 0; kk < 32; ++kk) {
                float4 ra = *(const float4*)&vT[kk * PADA + r0];
                float4 rb = *(const float4*)&vT[kk * PADA + r0 + 4];
                ull rp[4] = { ((const ull*)&ra)[0], ((const ull*)&ra)[1],
                              ((const ull*)&rb)[0], ((const ull*)&rb)[1] };
                float4 bv = *(const float4*)&Bc[(kk << 5) + c0];
                ull bd[4] = { pk2(bv.x), pk2(bv.y), pk2(bv.z), pk2(bv.w) };
                if (kk == 0) {
                    #pragma unroll
                    for (int p = 0; p < 4; ++p)
                        #pragma unroll
                        for (int c = 0; c < 4; ++c)
                            qa[p][c] = mul2(rp[p], bd[c]);
                } else {
                    #pragma unroll
                    for (int p = 0; p < 4; ++p)
                        #pragma unroll
                        for (int c = 0; c < 4; ++c)
                            fma2(qa[p][c], rp[p], bd[c]);
                }
            }
            float4 ua = *(const float4*)&uT[ii * PADA + r0];
            float4 ub = *(const float4*)&uT[ii * PADA + r0 + 4];
            ull up[4] = { ((const ull*)&ua)[0], ((const ull*)&ua)[1],
                          ((const ull*)&ub)[0], ((const ull*)&ub)[1] };
            #pragma unroll
            for (int p = 0; p < 4; ++p)
                #pragma unroll
                for (int c = 0; c < 4; ++c)
                    fma2(acc[p][c], up[p], qa[p][c]);
        } else {
            const float* S = (s == 0) ? uT : vT;
            #pragma unroll
            for (int kk = 0; kk < 32; ++kk) {
                float4 ra = *(const float4*)&S[kk * PADA + r0];
                float4 rb = *(const float4*)&S[kk * PADA + r0 + 4];
                ull rp[4] = { ((const ull*)&ra)[0], ((const ull*)&ra)[1],
                              ((const ull*)&rb)[0], ((const ull*)&rb)[1] };
                float4 bv = *(const float4*)&Bc[(kk << 5) + c0];
                ull bd[4] = { pk2(bv.x), pk2(bv.y), pk2(bv.z), pk2(bv.w) };
                #pragma unroll
                for (int p = 0; p < 4; ++p)
                    #pragma unroll
                    for (int c = 0; c < 4; ++c)
                        fma2(acc[p][c], rp[p], bd[c]);
            }
        }
    }

    float4 bav = *(const float4*)&ba[c0];
    int hoff = leftside ? 0 : 32;
    #pragma unroll
    for (int p = 0; p < 4; ++p) {
        float2 v0 = up2(acc[p][0]);
        float2 v1 = up2(acc[p][1]);
        float2 v2 = up2(acc[p][2]);
        float2 v3 = up2(acc[p][3]);
        float4 oA = { v0.x + bav.x, v1.x + bav.y, v2.x + bav.z, v3.x + bav.w };
        float4 oB = { v0.y + bav.x, v1.y + bav.y, v2.y + bav.z, v3.y + bav.w };
        *(float4*)&g_lr[(size_t)(n0 + r0 + 2 * p)     * 64 + hoff + c0] = oA;
        *(float4*)&g_lr[(size_t)(n0 + r0 + 2 * p + 1) * 64 + hoff + c0] = oB;
    }
}

// =====================================================================
// Kernel B: raw mma.sync bf16 hi/lo split, software-pipelined:
// materialize A[s+1] overlaps MMA(s); A double-buffered, B 3-ring.
// 512 threads; warp grid 4M x 4N; warp tile 32x32.
// =====================================================================
#define SM_LR   0             // float[128*64]                    32768
#define SM_AHI  32768         // 2 x bf16[128][64] swizzled       32768
#define SM_ALO  65536         // 2 x bf16[128][64] swizzled       32768
#define SM_B    98304         // 3 x (hi 16384 + lo 16384)        98304
#define SM_BS1  196608        // float[128]
#define SM_W2   197120        // float[128]
#define SM_DS   197632        // float[128][4]
#define KM_SMEM 199680

__global__ __launch_bounds__(512, 1) void k_main(
    const float* __restrict__ bs1, const float* __restrict__ Ws2,
    const float* __restrict__ bs2, float* __restrict__ out)
{
    extern __shared__ __align__(16) char sm[];
    float* LR = (float*)(sm + SM_LR);
    uint32_t sb = s2u(sm);
    int tid = threadIdx.x;
    int wid = tid >> 5, lane = tid & 31;
    int n0 = blockIdx.x << 7;

    // prefetch B chunks 0,1 (32KB each: 2048 x 16B)
    #pragma unroll
    for (int p = 0; p < 2; ++p) {
        #pragma unroll
        for (int q = 0; q < 2; ++q) {
            int e = q * 512 + tid;   // 1024 per half
            cpa16(sb + SM_B + p * 32768 + e * 16,         (const char*)g_whi + (size_t)p * 16384 + e * 16);
            cpa16(sb + SM_B + p * 32768 + 16384 + e * 16, (const char*)g_wlo + (size_t)p * 16384 + e * 16);
        }
        cpa_commit();
    }

    #pragma unroll
    for (int it = 0; it < 4; ++it) {
        int e4 = it * 512 + tid;
        int r = e4 >> 4, q = e4 & 15;
        *(float4*)&LR[r * 64 + q * 4] = *(const float4*)&g_lr[(size_t)(n0 + r) * 64 + q * 4];
    }
    if (tid < 128) {
        ((float*)(sm + SM_BS1))[tid] = bs1[tid];
        ((float*)(sm + SM_W2))[tid]  = Ws2[tid];
    }
    __syncthreads();

    float acc[2][4][4];
    #pragma unroll
    for (int mt = 0; mt < 2; ++mt)
        #pragma unroll
        for (int nt = 0; nt < 4; ++nt)
            #pragma unroll
            for (int e = 0; e < 4; ++e) acc[mt][nt][e] = 0.f;

    int m0w = (wid >> 2) * 32, n0w = (wid & 3) * 32;
    // ldmatrix lane geometry
    int li = lane & 7, lt = lane >> 3;           // tile index within x4
    int rA_off = li + ((lt & 1) << 3);           // A: row within 16-row tile
    int segA_h = lt >> 1;                        // A: k-seg half
    int hB = lt & 1;                             // B: k-seg half
    int lobB = (lt >> 1) * 16384;                // B: lanes 16-31 -> lo buffer

    int row8 = tid >> 5 << 0;                    // placeholder (unused)
    (void)row8;

    // ---- materialize helper (chunk c into A buffer c&1) ----
    auto materialize = [&](int c) {
        char* ahi = sm + SM_AHI + (c & 1) * 16384;
        char* alo = sm + SM_ALO + (c & 1) * 16384;
        #pragma unroll
        for (int it = 0; it < 8; ++it) {
            int p = it * 512 + tid;              // 4096 pairs
            int row = p >> 5, t0 = (p & 31) * 2;
            float f0, f1;
            if (c == 0) {
                float2 lv = *(const float2*)&LR[row * 64 + t0];
                f0 = lv.x; f1 = lv.y;
            } else {
                int i = 2 * (c - 1) + (t0 >> 5), j = t0 & 31;
                float Lv = LR[row * 64 + i];
                float2 rv = *(const float2*)&LR[row * 64 + 32 + j];
                f0 = Lv * rv.x;
                f1 = Lv * rv.y;
            }
            uint32_t hp;
            asm("cvt.rn.bf16x2.f32 %0, %1, %2;" : "=r"(hp) : "f"(f1), "f"(f0));
            float b0 = __uint_as_float(hp << 16);
            float b1 = __uint_as_float(hp & 0xffff0000u);
            float l0 = f0 - b0, l1 = f1 - b1;
            uint32_t lp;
            asm("cvt.rn.bf16x2.f32 %0, %1, %2;" : "=r"(lp) : "f"(l1), "f"(l0));
            uint32_t off = row * 128 + ((((t0 >> 3) ^ (row & 7))) << 4) + (t0 & 7) * 2;
            *(uint32_t*)(ahi + off) = hp;
            *(uint32_t*)(alo + off) = lp;
        }
    };

    // prologue: materialize chunk 0
    materialize(0);
    __syncthreads();

    for (int s = 0; s < 17; ++s) {
        cpa_wait<1>();                           // B chunk s landed
        if (s + 2 < 17) {                        // prefetch B s+2 into ring slot freed at s-1
            #pragma unroll
            for (int q = 0; q < 2; ++q) {
                int e = q * 512 + tid;
                cpa16(sb + SM_B + ((s + 2) % 3) * 32768 + e * 16,
                      (const char*)g_whi + (size_t)(s + 2) * 16384 + e * 16);
                cpa16(sb + SM_B + ((s + 2) % 3) * 32768 + 16384 + e * 16,
                      (const char*)g_wlo + (size_t)(s + 2) * 16384 + e * 16);
            }
        }
        cpa_commit();

        // overlap: materialize A[s+1] while MMAs consume A[s]
        if (s + 1 < 17) materialize(s + 1);

        uint32_t Bb = sb + SM_B + (s % 3) * 32768;
        uint32_t Ab = sb + SM_AHI + (s & 1) * 16384;
        #pragma unroll
        for (int ks = 0; ks < 4; ++ks) {
            uint32_t bf[4][4];
            #pragma unroll
            for (int nt = 0; nt < 4; ++nt) {
                int row = n0w + nt * 8 + li;
                uint32_t addr = Bb + lobB + row * 128 + ((((2 * ks + hB) ^ (row & 7))) << 4);
                ldsm4(bf[nt], addr);
            }
            #pragma unroll
            for (int mt = 0; mt < 2; ++mt) {
                int row = m0w + mt * 16 + rA_off;
                int seg = 2 * ks + segA_h;
                uint32_t addr = Ab + row * 128 + (((seg ^ (row & 7))) << 4);
                uint32_t ah[4], al[4];
                ldsm4(ah, addr);
                ldsm4(al, addr + 32768);         // ALO region
                #pragma unroll
                for (int nt = 0; nt < 4; ++nt) {
                    mma_bf16(acc[mt][nt], ah, bf[nt]);          // hi*hi
                    mma_bf16(acc[mt][nt], ah, bf[nt] + 2);      // hi*lo
                    mma_bf16(acc[mt][nt], al, bf[nt]);          // lo*hi
                }
            }
        }
        __syncthreads();                         // A[s+1] complete + B slot free
    }

    // epilogue: +bs1, elu, dot Ws2, reduce
    const float* bs1s = (const float*)(sm + SM_BS1);
    const float* w2s  = (const float*)(sm + SM_W2);
    float* Dsum = (float*)(sm + SM_DS);
    int q = lane >> 2, c2 = (lane & 3) * 2;
    float bias2 = bs2[0];
    #pragma unroll
    for (int mt = 0; mt < 2; ++mt) {
        float s0 = 0.f, s1 = 0.f;
        #pragma unroll
        for (int nt = 0; nt < 4; ++nt) {
            int col = n0w + nt * 8 + c2;
            float2 bv = *(const float2*)&bs1s[col];
            float2 wv = *(const float2*)&w2s[col];
            float* d = acc[mt][nt];
            float x0 = d[0] + bv.x, x1 = d[1] + bv.y;
            float x2 = d[2] + bv.x, x3 = d[3] + bv.y;
            float h0 = x0 > 0.f ? x0 : expm1f(x0);
            float h1 = x1 > 0.f ? x1 : expm1f(x1);
            float h2 = x2 > 0.f ? x2 : expm1f(x2);
            float h3 = x3 > 0.f ? x3 : expm1f(x3);
            s0 = fmaf(h0, wv.x, fmaf(h1, wv.y, s0));
            s1 = fmaf(h2, wv.x, fmaf(h3, wv.y, s1));
        }
        s0 += __shfl_xor_sync(0xffffffffu, s0, 1);
        s0 += __shfl_xor_sync(0xffffffffu, s0, 2);
        s1 += __shfl_xor_sync(0xffffffffu, s1, 1);
        s1 += __shfl_xor_sync(0xffffffffu, s1, 2);
        if ((lane & 3) == 0) {
            int row = m0w + mt * 16 + q;
            Dsum[row * 4 + (wid & 3)] = s0;
            Dsum[(row + 8) * 4 + (wid & 3)] = s1;
        }
    }
    __syncthreads();
    if (tid < 128) {
        float v = Dsum[tid * 4] + Dsum[tid * 4 + 1] + Dsum[tid * 4 + 2] + Dsum[tid * 4 + 3];
        out[n0 + tid] = v + bias2;
    }
}

extern "C" void kernel_launch(void* const* d_in, const int* in_sizes, int n_in,
                              void* d_out, int out_size)
{
    const float* concepts = (const float*)d_in[0];
    const float* Wn  = (const float*)d_in[1];
    const float* bn  = (const float*)d_in[2];
    const float* Wa  = (const float*)d_in[3];
    const float* ba  = (const float*)d_in[4];
    const float* Ws1 = (const float*)d_in[5];
    const float* bs1 = (const float*)d_in[6];
    const float* Ws2 = (const float*)d_in[7];
    const float* bs2 = (const float*)d_in[8];
    const void*  idx = d_in[9];
    int nrows = in_sizes[9] / 4;

    static int inited = 0;
    if (!inited) {
        cudaFuncSetAttribute(k_main, cudaFuncAttributeMaxDynamicSharedMemorySize, KM_SMEM);
        inited = 1;
    }

    k_conv<<<(17 * 64 * 128 + 255) / 256, 256>>>(Ws1);
    k_lr<<<(nrows / 128) * 2, 128>>>(concepts, Wn, bn, Wa, ba, idx, nrows);
    k_main<<<nrows / 128, 512, KM_SMEM>>>(bs1, Ws2, bs2, (float*)d_out);
}

// round 12
// speedup vs baseline: 1.0114x; 1.0114x over previous
#include <cuda_runtime.h>
#include <cuda_bf16.h>
#include <cstdint>

#define NROWS_MAX 65536
typedef unsigned long long ull;

// scratch: left/right activations [n][0..31]=left, [n][32..63]=right
__device__ __align__(16) float g_lr[(size_t)NROWS_MAX * 64];
// pre-split Ws1, bf16, N-major, XOR-swizzled: [17 chunks][128 n][64 k]
__device__ __align__(16) __nv_bfloat16 g_whi[17 * 8192];
__device__ __align__(16) __nv_bfloat16 g_wlo[17 * 8192];
// pre-split Wa, bf16, N-major, XOR-swizzled: [17 chunks][32 n][64 k]
__device__ __align__(16) __nv_bfloat16 g_wahi[17 * 2048];
__device__ __align__(16) __nv_bfloat16 g_walo[17 * 2048];

// ---------- cp.async ----------
__device__ __forceinline__ uint32_t s2u(const void* p) {
    uint32_t a;
    asm("{ .reg .u64 t; cvta.to.shared.u64 t, %1; cvt.u32.u64 %0, t; }" : "=r"(a) : "l"(p));
    return a;
}
__device__ __forceinline__ void cpa16(uint32_t dst, const void* src) {
    asm volatile("cp.async.ca.shared.global [%0], [%1], 16;" :: "r"(dst), "l"(src));
}
__device__ __forceinline__ void cpa_commit() { asm volatile("cp.async.commit_group;"); }
template<int N> __device__ __forceinline__ void cpa_wait() {
    asm volatile("cp.async.wait_group %0;" :: "n"(N));
}
// ---------- tensor primitives ----------
__device__ __forceinline__ void ldsm4(uint32_t* r, uint32_t a) {
    asm volatile("ldmatrix.sync.aligned.m8n8.x4.shared.b16 {%0,%1,%2,%3}, [%4];"
        : "=r"(r[0]), "=r"(r[1]), "=r"(r[2]), "=r"(r[3]) : "r"(a));
}
__device__ __forceinline__ void mma_bf16(float* d, const uint32_t* a, const uint32_t* b) {
    asm volatile("mma.sync.aligned.m16n8k16.row.col.f32.bf16.bf16.f32 "
        "{%0,%1,%2,%3}, {%4,%5,%6,%7}, {%8,%9}, {%0,%1,%2,%3};"
        : "+f"(d[0]), "+f"(d[1]), "+f"(d[2]), "+f"(d[3])
        : "r"(a[0]), "r"(a[1]), "r"(a[2]), "r"(a[3]), "r"(b[0]), "r"(b[1]));
}
// split a pair of floats into packed bf16 hi / lo
__device__ __forceinline__ void split2(float f0, float f1, uint32_t& hp, uint32_t& lp) {
    asm("cvt.rn.bf16x2.f32 %0, %1, %2;" : "=r"(hp) : "f"(f1), "f"(f0));
    float b0 = __uint_as_float(hp << 16);
    float b1 = __uint_as_float(hp & 0xffff0000u);
    asm("cvt.rn.bf16x2.f32 %0, %1, %2;" : "=r"(lp) : "f"(f1 - b1), "f"(f0 - b0));
}

// =====================================================================
// Converters: split weights -> bf16 hi/lo, N-major swizzled
// =====================================================================
__global__ void k_conv(const float* __restrict__ Ws1) {
    int gid = blockIdx.x * 256 + threadIdx.x;
    if (gid >= 17 * 64 * 128) return;
    int s = gid >> 13, rem = gid & 8191;
    int k = rem >> 7, n = rem & 127;
    float w = Ws1[(s * 64 + k) * 128 + n];
    __nv_bfloat16 hi = __float2bfloat16(w);
    __nv_bfloat16 lo = __float2bfloat16(w - __bfloat162float(hi));
    uint32_t off = (uint32_t)s * 16384 + n * 128 + ((((k >> 3) ^ (n & 7))) << 4) + (k & 7) * 2;
    *(__nv_bfloat16*)((char*)g_whi + off) = hi;
    *(__nv_bfloat16*)((char*)g_wlo + off) = lo;
}
__global__ void k_conv_a(const float* __restrict__ Wa) {
    int gid = blockIdx.x * 256 + threadIdx.x;
    if (gid >= 17 * 64 * 32) return;
    int s = gid >> 11, rem = gid & 2047;
    int k = rem >> 5, n = rem & 31;
    float w = Wa[(s * 64 + k) * 32 + n];
    __nv_bfloat16 hi = __float2bfloat16(w);
    __nv_bfloat16 lo = __float2bfloat16(w - __bfloat162float(hi));
    uint32_t off = (uint32_t)s * 4096 + n * 128 + ((((k >> 3) ^ (n & 7))) << 4) + (k & 7) * 2;
    *(__nv_bfloat16*)((char*)g_wahi + off) = hi;
    *(__nv_bfloat16*)((char*)g_walo + off) = lo;
}

// =====================================================================
// Kernel A (MMA): per 128-row tile, compute left & right via one
// M=256 (F1 stacked on F2), N=32, K=1088 GEMM. bf16 hi/lo 3-pass.
// 512 threads; warp grid 8M x 2N; warp tile 32x16.
// =====================================================================
#define LA_LR    0            // float[2][128][64]               65536
#define LA_AHI   65536        // bf16[256][64] swizzled          32768 (Atemp overlay pre-MMA)
#define LA_ALO   98304        // bf16[256][64] swizzled          32768
#define LA_B     131072       // 3 x (hi 4096 + lo 4096)         24576
#define LA_WN    155648       // float[32][32]                    4096
#define LA_BN    159744       // float[32]
#define LA_BA    159872       // float[32]
#define LA_SMEM  160256

__global__ __launch_bounds__(512, 1) void k_lrm(
    const float* __restrict__ concepts, const float* __restrict__ Wn,
    const float* __restrict__ bn, const float* __restrict__ ba,
    const void* __restrict__ idxp)
{
    extern __shared__ __align__(16) char sm[];
    float* LR = (float*)(sm + LA_LR);           // side s at +s*8192 floats
    uint32_t sb = s2u(sm);
    int tid = threadIdx.x;
    int wid = tid >> 5, lane = tid & 31;
    int n0 = blockIdx.x << 7;

    // prefetch B chunks 0,1 (8KB each = hi 4KB + lo 4KB)
    {
        int half = tid >> 8, e = tid & 255;
        #pragma unroll
        for (int p = 0; p < 2; ++p) {
            cpa16(sb + LA_B + p * 8192 + half * 4096 + e * 16,
                  (half ? (const char*)g_walo : (const char*)g_wahi) + (size_t)p * 4096 + e * 16);
            cpa_commit();
        }
    }

    // load Wn, bn, ba
    {
        float* Wns = (float*)(sm + LA_WN);
        for (int e = tid; e < 1024; e += 512) Wns[e] = Wn[e];
        if (tid < 32) {
            ((float*)(sm + LA_BN))[tid] = bn[tid];
            ((float*)(sm + LA_BA))[tid] = ba[tid];
        }
    }

    // idx dtype detection
    const int* idx32 = (const int*)idxp;
    bool is64 = (idx32[1] == 0) & (idx32[3] == 0) & (idx32[5] == 0) & (idx32[7] == 0);
    const long long* idx64 = (const long long*)idxp;

    // gather: b -> LR1[.,32+], c -> LR2[.,0+], d -> LR2[.,32+], a -> Atemp
    float* Atemp = (float*)(sm + LA_AHI);       // overlay, consumed before materialize
    for (int e = tid; e < 4096; e += 512) {
        int row = e >> 5, col = e & 31;
        long long base = (long long)(n0 + row) * 4;
        long long ia = is64 ? idx64[base]     : (long long)idx32[base];
        long long ib = is64 ? idx64[base + 1] : (long long)idx32[base + 1];
        long long ic = is64 ? idx64[base + 2] : (long long)idx32[base + 2];
        long long id = is64 ? idx64[base + 3] : (long long)idx32[base + 3];
        Atemp[row * 32 + col]        = concepts[ia * 32 + col];
        LR[row * 64 + 32 + col]      = concepts[ib * 32 + col];
        LR[8192 + row * 64 + col]      = concepts[ic * 32 + col];
        LR[8192 + row * 64 + 32 + col] = concepts[id * 32 + col];
    }
    __syncthreads();

    // na = a @ Wn + bn -> LR1[.,0..31]
    {
        const float* Wns = (const float*)(sm + LA_WN);
        const float* bns = (const float*)(sm + LA_BN);
        for (int e = tid; e < 4096; e += 512) {
            int row = e >> 5, col = e & 31;
            float acc = bns[col];
            #pragma unroll
            for (int i = 0; i < 32; ++i)
                acc = fmaf(Atemp[row * 32 + i], Wns[i * 32 + col], acc);
            LR[row * 64 + col] = acc;
        }
    }
    __syncthreads();    // Atemp fully consumed; A region reusable

    float acc[2][2][4];
    #pragma unroll
    for (int mt = 0; mt < 2; ++mt)
        #pragma unroll
        for (int nt = 0; nt < 2; ++nt)
            #pragma unroll
            for (int e = 0; e < 4; ++e) acc[mt][nt][e] = 0.f;

    int m0w = (wid >> 1) * 32, n0w = (wid & 1) * 16;
    int li = lane & 7, lt = lane >> 3;
    int rA_off = li + ((lt & 1) << 3);
    int segA_h = lt >> 1;
    int hB = lt & 1;
    int lobB = (lt >> 1) * 4096;
    int halfc = tid >> 8, ec = tid & 255;       // B-copy lane

    for (int s = 0; s < 17; ++s) {
        // materialize feature chunk s (8192 pairs over 256 MMA rows)
        #pragma unroll
        for (int it = 0; it < 16; ++it) {
            int p = it * 512 + tid;
            int row = p >> 5, t0 = (p & 31) * 2;
            const float* LRs = LR + (row >> 7) * 8192;
            int lrow = row & 127;
            float f0, f1;
            if (s == 0) {
                float2 lv = *(const float2*)&LRs[lrow * 64 + t0];
                f0 = lv.x; f1 = lv.y;
            } else {
                int i = 2 * (s - 1) + (t0 >> 5), j = t0 & 31;
                float Lv = LRs[lrow * 64 + i];
                float2 rv = *(const float2*)&LRs[lrow * 64 + 32 + j];
                f0 = Lv * rv.x;
                f1 = Lv * rv.y;
            }
            uint32_t hp, lp;
            split2(f0, f1, hp, lp);
            uint32_t off = row * 128 + ((((t0 >> 3) ^ (row & 7))) << 4) + (t0 & 7) * 2;
            *(uint32_t*)(sm + LA_AHI + off) = hp;
            *(uint32_t*)(sm + LA_ALO + off) = lp;
        }
        cpa_wait<1>();
        __syncthreads();                         // A + B chunk s visible

        if (s + 2 < 17) {
            cpa16(sb + LA_B + ((s + 2) % 3) * 8192 + halfc * 4096 + ec * 16,
                  (halfc ? (const char*)g_walo : (const char*)g_wahi) + (size_t)(s + 2) * 4096 + ec * 16);
        }
        cpa_commit();

        uint32_t Bb = sb + LA_B + (s % 3) * 8192;
        #pragma unroll
        for (int ks = 0; ks < 4; ++ks) {
            uint32_t bf[2][4];
            #pragma unroll
            for (int nt = 0; nt < 2; ++nt) {
                int row = n0w + nt * 8 + li;
                uint32_t addr = Bb + lobB + row * 128 + ((((2 * ks + hB) ^ (row & 7))) << 4);
                ldsm4(bf[nt], addr);
            }
            #pragma unroll
            for (int mt = 0; mt < 2; ++mt) {
                int row = m0w + mt * 16 + rA_off;
                int seg = 2 * ks + segA_h;
                uint32_t addr = sb + LA_AHI + row * 128 + (((seg ^ (row & 7))) << 4);
                uint32_t ah[4], al[4];
                ldsm4(ah, addr);
                ldsm4(al, addr + 32768);
                #pragma unroll
                for (int nt = 0; nt < 2; ++nt) {
                    mma_bf16(acc[mt][nt], ah, bf[nt]);          // hi*hi
                    mma_bf16(acc[mt][nt], ah, bf[nt] + 2);      // hi*lo
                    mma_bf16(acc[mt][nt], al, bf[nt]);          // lo*hi
                }
            }
        }
        __syncthreads();                         // A consumed; safe to rewrite
    }

    // epilogue: +ba, write g_lr (rows 0-127 -> left, 128-255 -> right)
    const float* bas = (const float*)(sm + LA_BA);
    int q = lane >> 2, c2 = (lane & 3) * 2;
    #pragma unroll
    for (int mt = 0; mt < 2; ++mt) {
        #pragma unroll
        for (int nt = 0; nt < 2; ++nt) {
            int col = n0w + nt * 8 + c2;
            float bax = bas[col], bay = bas[col + 1];
            int gr0 = m0w + mt * 16 + q;
            int gr1 = gr0 + 8;
            float* d = acc[mt][nt];
            size_t o0 = (size_t)(n0 + (gr0 & 127)) * 64 + (gr0 >> 7) * 32 + col;
            size_t o1 = (size_t)(n0 + (gr1 & 127)) * 64 + (gr1 >> 7) * 32 + col;
            g_lr[o0]     = d[0] + bax;
            g_lr[o0 + 1] = d[1] + bay;
            g_lr[o1]     = d[2] + bax;
            g_lr[o1 + 1] = d[3] + bay;
        }
    }
}

// =====================================================================
// Kernel B: raw mma.sync bf16 hi/lo split (R8 proven form).
// 512 threads; warp grid 4M x 4N; warp tile 32x32.
// =====================================================================
#define SM_LR   0             // float[128*64]                    32768
#define SM_AHI  32768         // bf16[128][64] swizzled           16384
#define SM_ALO  49152         // bf16[128][64] swizzled           16384
#define SM_B    65536         // 3 x (hi 16384 + lo 16384)        98304
#define SM_BS1  163840        // float[128]
#define SM_W2   164352        // float[128]
#define SM_DS   164864        // float[128][4]
#define KM_SMEM 166912

__global__ __launch_bounds__(512, 1) void k_main(
    const float* __restrict__ bs1, const float* __restrict__ Ws2,
    const float* __restrict__ bs2, float* __restrict__ out)
{
    extern __shared__ __align__(16) char sm[];
    float* LR = (float*)(sm + SM_LR);
    uint32_t sb = s2u(sm);
    int tid = threadIdx.x;
    int wid = tid >> 5, lane = tid & 31;
    int n0 = blockIdx.x << 7;

    // prefetch B chunks 0,1 (32KB each: 2048 x 16B)
    #pragma unroll
    for (int p = 0; p < 2; ++p) {
        #pragma unroll
        for (int q = 0; q < 2; ++q) {
            int e = q * 512 + tid;
            cpa16(sb + SM_B + p * 32768 + e * 16,         (const char*)g_whi + (size_t)p * 16384 + e * 16);
            cpa16(sb + SM_B + p * 32768 + 16384 + e * 16, (const char*)g_wlo + (size_t)p * 16384 + e * 16);
        }
        cpa_commit();
    }

    #pragma unroll
    for (int it = 0; it < 4; ++it) {
        int e4 = it * 512 + tid;
        int r = e4 >> 4, q = e4 & 15;
        *(float4*)&LR[r * 64 + q * 4] = *(const float4*)&g_lr[(size_t)(n0 + r) * 64 + q * 4];
    }
    if (tid < 128) {
        ((float*)(sm + SM_BS1))[tid] = bs1[tid];
        ((float*)(sm + SM_W2))[tid]  = Ws2[tid];
    }
    __syncthreads();

    float acc[2][4][4];
    #pragma unroll
    for (int mt = 0; mt < 2; ++mt)
        #pragma unroll
        for (int nt = 0; nt < 4; ++nt)
            #pragma unroll
            for (int e = 0; e < 4; ++e) acc[mt][nt][e] = 0.f;

    int m0w = (wid >> 2) * 32, n0w = (wid & 3) * 32;
    int li = lane & 7, lt = lane >> 3;
    int rA_off = li + ((lt & 1) << 3);
    int segA_h = lt >> 1;
    int hB = lt & 1;
    int lobB = (lt >> 1) * 16384;

    for (int s = 0; s < 17; ++s) {
        // materialize feature chunk s into Ahi/Alo (pairs; swizzled)
        #pragma unroll
        for (int it = 0; it < 8; ++it) {
            int p = it * 512 + tid;
            int row = p >> 5, t0 = (p & 31) * 2;
            float f0, f1;
            if (s == 0) {
                float2 lv = *(const float2*)&LR[row * 64 + t0];
                f0 = lv.x; f1 = lv.y;
            } else {
                int i = 2 * (s - 1) + (t0 >> 5), j = t0 & 31;
                float Lv = LR[row * 64 + i];
                float2 rv = *(const float2*)&LR[row * 64 + 32 + j];
                f0 = Lv * rv.x;
                f1 = Lv * rv.y;
            }
            uint32_t hp, lp;
            split2(f0, f1, hp, lp);
            uint32_t off = row * 128 + ((((t0 >> 3) ^ (row & 7))) << 4) + (t0 & 7) * 2;
            *(uint32_t*)(sm + SM_AHI + off) = hp;
            *(uint32_t*)(sm + SM_ALO + off) = lp;
        }
        cpa_wait<1>();
        __syncthreads();                         // A visible + B chunk s visible

        if (s + 2 < 17) {
            #pragma unroll
            for (int q = 0; q < 2; ++q) {
                int e = q * 512 + tid;
                cpa16(sb + SM_B + ((s + 2) % 3) * 32768 + e * 16,
                      (const char*)g_whi + (size_t)(s + 2) * 16384 + e * 16);
                cpa16(sb + SM_B + ((s + 2) % 3) * 32768 + 16384 + e * 16,
                      (const char*)g_wlo + (size_t)(s + 2) * 16384 + e * 16);
            }
        }
        cpa_commit();

        uint32_t Bb = sb + SM_B + (s % 3) * 32768;
        #pragma unroll
        for (int ks = 0; ks < 4; ++ks) {
            uint32_t bf[4][4];
            #pragma unroll
            for (int nt = 0; nt < 4; ++nt) {
                int row = n0w + nt * 8 + li;
                uint32_t addr = Bb + lobB + row * 128 + ((((2 * ks + hB) ^ (row & 7))) << 4);
                ldsm4(bf[nt], addr);
            }
            #pragma unroll
            for (int mt = 0; mt < 2; ++mt) {
                int row = m0w + mt * 16 + rA_off;
                int seg = 2 * ks + segA_h;
                uint32_t addr = sb + SM_AHI + row * 128 + (((seg ^ (row & 7))) << 4);
                uint32_t ah[4], al[4];
                ldsm4(ah, addr);
                ldsm4(al, addr + 16384);
                #pragma unroll
                for (int nt = 0; nt < 4; ++nt) {
                    mma_bf16(acc[mt][nt], ah, bf[nt]);          // hi*hi
                    mma_bf16(acc[mt][nt], ah, bf[nt] + 2);      // hi*lo
                    mma_bf16(acc[mt][nt], al, bf[nt]);          // lo*hi
                }
            }
        }
        __syncthreads();
    }

    // epilogue: +bs1, elu, dot Ws2, reduce
    const float* bs1s = (const float*)(sm + SM_BS1);
    const float* w2s  = (const float*)(sm + SM_W2);
    float* Dsum = (float*)(sm + SM_DS);
    int q = lane >> 2, c2 = (lane & 3) * 2;
    float bias2 = bs2[0];
    #pragma unroll
    for (int mt = 0; mt < 2; ++mt) {
        float s0 = 0.f, s1 = 0.f;
        #pragma unroll
        for (int nt = 0; nt < 4; ++nt) {
            int col = n0w + nt * 8 + c2;
            float2 bv = *(const float2*)&bs1s[col];
            float2 wv = *(const float2*)&w2s[col];
            float* d = acc[mt][nt];
            float x0 = d[0] + bv.x, x1 = d[1] + bv.y;
            float x2 = d[2] + bv.x, x3 = d[3] + bv.y;
            float h0 = x0 > 0.f ? x0 : expm1f(x0);
            float h1 = x1 > 0.f ? x1 : expm1f(x1);
            float h2 = x2 > 0.f ? x2 : expm1f(x2);
            float h3 = x3 > 0.f ? x3 : expm1f(x3);
            s0 = fmaf(h0, wv.x, fmaf(h1, wv.y, s0));
            s1 = fmaf(h2, wv.x, fmaf(h3, wv.y, s1));
        }
        s0 += __shfl_xor_sync(0xffffffffu, s0, 1);
        s0 += __shfl_xor_sync(0xffffffffu, s0, 2);
        s1 += __shfl_xor_sync(0xffffffffu, s1, 1);
        s1 += __shfl_xor_sync(0xffffffffu, s1, 2);
        if ((lane & 3) == 0) {
            int row = m0w + mt * 16 + q;
            Dsum[row * 4 + (wid & 3)] = s0;
            Dsum[(row + 8) * 4 + (wid & 3)] = s1;
        }
    }
    __syncthreads();
    if (tid < 128) {
        float v = Dsum[tid * 4] + Dsum[tid * 4 + 1] + Dsum[tid * 4 + 2] + Dsum[tid * 4 + 3];
        out[n0 + tid] = v + bias2;
    }
}

extern "C" void kernel_launch(void* const* d_in, const int* in_sizes, int n_in,
                              void* d_out, int out_size)
{
    const float* concepts = (const float*)d_in[0];
    const float* Wn  = (const float*)d_in[1];
    const float* bn  = (const float*)d_in[2];
    const float* Wa  = (const float*)d_in[3];
    const float* ba  = (const float*)d_in[4];
    const float* Ws1 = (const float*)d_in[5];
    const float* bs1 = (const float*)d_in[6];
    const float* Ws2 = (const float*)d_in[7];
    const float* bs2 = (const float*)d_in[8];
    const void*  idx = d_in[9];
    int nrows = in_sizes[9] / 4;

    static int inited = 0;
    if (!inited) {
        cudaFuncSetAttribute(k_main, cudaFuncAttributeMaxDynamicSharedMemorySize, KM_SMEM);
        cudaFuncSetAttribute(k_lrm,  cudaFuncAttributeMaxDynamicSharedMemorySize, LA_SMEM);
        inited = 1;
    }

    k_conv<<<(17 * 64 * 128 + 255) / 256, 256>>>(Ws1);
    k_conv_a<<<(17 * 64 * 32 + 255) / 256, 256>>>(Wa);
    k_lrm<<<nrows / 128, 512, LA_SMEM>>>(concepts, Wn, bn, ba, idx);
    k_main<<<nrows / 128, 512, KM_SMEM>>>(bs1, Ws2, bs2, (float*)d_out);
}

// round 14
// speedup vs baseline: 1.0541x; 1.0422x over previous
#include <cuda_runtime.h>
#include <cuda_bf16.h>
#include <cstdint>

#define NROWS_MAX 65536
typedef unsigned long long ull;

// scratch: left/right activations [n][0..31]=left, [n][32..63]=right
__device__ __align__(16) float g_lr[(size_t)NROWS_MAX * 64];
// pre-split Ws1, bf16, N-major, XOR-swizzled: [17 chunks][128 n][64 k]
__device__ __align__(16) __nv_bfloat16 g_whi[17 * 8192];
__device__ __align__(16) __nv_bfloat16 g_wlo[17 * 8192];
// pre-split Wa, bf16, N-major, XOR-swizzled: [17 chunks][32 n][64 k]
__device__ __align__(16) __nv_bfloat16 g_wahi[17 * 2048];
__device__ __align__(16) __nv_bfloat16 g_walo[17 * 2048];

// ---------- cp.async ----------
__device__ __forceinline__ uint32_t s2u(const void* p) {
    uint32_t a;
    asm("{ .reg .u64 t; cvta.to.shared.u64 t, %1; cvt.u32.u64 %0, t; }" : "=r"(a) : "l"(p));
    return a;
}
__device__ __forceinline__ void cpa16(uint32_t dst, const void* src) {
    asm volatile("cp.async.ca.shared.global [%0], [%1], 16;" :: "r"(dst), "l"(src));
}
__device__ __forceinline__ void cpa_commit() { asm volatile("cp.async.commit_group;"); }
template<int N> __device__ __forceinline__ void cpa_wait() {
    asm volatile("cp.async.wait_group %0;" :: "n"(N));
}
// ---------- tensor primitives ----------
__device__ __forceinline__ void ldsm4(uint32_t* r, uint32_t a) {
    asm volatile("ldmatrix.sync.aligned.m8n8.x4.shared.b16 {%0,%1,%2,%3}, [%4];"
        : "=r"(r[0]), "=r"(r[1]), "=r"(r[2]), "=r"(r[3]) : "r"(a));
}
__device__ __forceinline__ void mma_bf16(float* d, const uint32_t* a, const uint32_t* b) {
    asm volatile("mma.sync.aligned.m16n8k16.row.col.f32.bf16.bf16.f32 "
        "{%0,%1,%2,%3}, {%4,%5,%6,%7}, {%8,%9}, {%0,%1,%2,%3};"
        : "+f"(d[0]), "+f"(d[1]), "+f"(d[2]), "+f"(d[3])
        : "r"(a[0]), "r"(a[1]), "r"(a[2]), "r"(a[3]), "r"(b[0]), "r"(b[1]));
}
// d = a*b (zero accumulator)
__device__ __forceinline__ void mma_bf16_c0(float* d, const uint32_t* a, const uint32_t* b) {
    asm volatile("mma.sync.aligned.m16n8k16.row.col.f32.bf16.bf16.f32 "
        "{%0,%1,%2,%3}, {%4,%5,%6,%7}, {%8,%9}, {%10,%11,%12,%13};"
        : "=f"(d[0]), "=f"(d[1]), "=f"(d[2]), "=f"(d[3])
        : "r"(a[0]), "r"(a[1]), "r"(a[2]), "r"(a[3]), "r"(b[0]), "r"(b[1]),
          "f"(0.f), "f"(0.f), "f"(0.f), "f"(0.f));
}
// split a pair of floats into packed bf16 hi / lo
__device__ __forceinline__ void split2(float f0, float f1, uint32_t& hp, uint32_t& lp) {
    asm("cvt.rn.bf16x2.f32 %0, %1, %2;" : "=r"(hp) : "f"(f1), "f"(f0));
    float b0 = __uint_as_float(hp << 16);
    float b1 = __uint_as_float(hp & 0xffff0000u);
    asm("cvt.rn.bf16x2.f32 %0, %1, %2;" : "=r"(lp) : "f"(f1 - b1), "f"(f0 - b0));
}

// =====================================================================
// Converters: split weights -> bf16 hi/lo, N-major swizzled
// =====================================================================
__global__ void k_conv(const float* __restrict__ Ws1) {
    int gid = blockIdx.x * 256 + threadIdx.x;
    if (gid >= 17 * 64 * 128) return;
    int s = gid >> 13, rem = gid & 8191;
    int k = rem >> 7, n = rem & 127;
    float w = Ws1[(s * 64 + k) * 128 + n];
    __nv_bfloat16 hi = __float2bfloat16(w);
    __nv_bfloat16 lo = __float2bfloat16(w - __bfloat162float(hi));
    uint32_t off = (uint32_t)s * 16384 + n * 128 + ((((k >> 3) ^ (n & 7))) << 4) + (k & 7) * 2;
    *(__nv_bfloat16*)((char*)g_whi + off) = hi;
    *(__nv_bfloat16*)((char*)g_wlo + off) = lo;
}
__global__ void k_conv_a(const float* __restrict__ Wa) {
    int gid = blockIdx.x * 256 + threadIdx.x;
    if (gid >= 17 * 64 * 32) return;
    int s = gid >> 11, rem = gid & 2047;
    int k = rem >> 5, n = rem & 31;
    float w = Wa[(s * 64 + k) * 32 + n];
    __nv_bfloat16 hi = __float2bfloat16(w);
    __nv_bfloat16 lo = __float2bfloat16(w - __bfloat162float(hi));
    uint32_t off = (uint32_t)s * 4096 + n * 128 + ((((k >> 3) ^ (n & 7))) << 4) + (k & 7) * 2;
    *(__nv_bfloat16*)((char*)g_wahi + off) = hi;
    *(__nv_bfloat16*)((char*)g_walo + off) = lo;
}

// =====================================================================
// Kernel A (MMA): per 128-row tile, left & right via M=256/N=32/K=1088
// bf16 hi/lo 3-pass GEMM. (R11 proven form, unchanged.)
// =====================================================================
#define LA_LR    0
#define LA_AHI   65536
#define LA_ALO   98304
#define LA_B     131072
#define LA_WN    155648
#define LA_BN    159744
#define LA_BA    159872
#define LA_SMEM  160256

__global__ __launch_bounds__(512, 1) void k_lrm(
    const float* __restrict__ concepts, const float* __restrict__ Wn,
    const float* __restrict__ bn, const float* __restrict__ ba,
    const void* __restrict__ idxp)
{
    extern __shared__ __align__(16) char sm[];
    float* LR = (float*)(sm + LA_LR);
    uint32_t sb = s2u(sm);
    int tid = threadIdx.x;
    int wid = tid >> 5, lane = tid & 31;
    int n0 = blockIdx.x << 7;

    {
        int half = tid >> 8, e = tid & 255;
        #pragma unroll
        for (int p = 0; p < 2; ++p) {
            cpa16(sb + LA_B + p * 8192 + half * 4096 + e * 16,
                  (half ? (const char*)g_walo : (const char*)g_wahi) + (size_t)p * 4096 + e * 16);
            cpa_commit();
        }
    }
    {
        float* Wns = (float*)(sm + LA_WN);
        for (int e = tid; e < 1024; e += 512) Wns[e] = Wn[e];
        if (tid < 32) {
            ((float*)(sm + LA_BN))[tid] = bn[tid];
            ((float*)(sm + LA_BA))[tid] = ba[tid];
        }
    }

    const int* idx32 = (const int*)idxp;
    bool is64 = (idx32[1] == 0) & (idx32[3] == 0) & (idx32[5] == 0) & (idx32[7] == 0);
    const long long* idx64 = (const long long*)idxp;

    float* Atemp = (float*)(sm + LA_AHI);
    for (int e = tid; e < 4096; e += 512) {
        int row = e >> 5, col = e & 31;
        long long base = (long long)(n0 + row) * 4;
        long long ia = is64 ? idx64[base]     : (long long)idx32[base];
        long long ib = is64 ? idx64[base + 1] : (long long)idx32[base + 1];
        long long ic = is64 ? idx64[base + 2] : (long long)idx32[base + 2];
        long long id = is64 ? idx64[base + 3] : (long long)idx32[base + 3];
        Atemp[row * 32 + col]        = concepts[ia * 32 + col];
        LR[row * 64 + 32 + col]      = concepts[ib * 32 + col];
        LR[8192 + row * 64 + col]      = concepts[ic * 32 + col];
        LR[8192 + row * 64 + 32 + col] = concepts[id * 32 + col];
    }
    __syncthreads();

    {
        const float* Wns = (const float*)(sm + LA_WN);
        const float* bns = (const float*)(sm + LA_BN);
        for (int e = tid; e < 4096; e += 512) {
            int row = e >> 5, col = e & 31;
            float acc = bns[col];
            #pragma unroll
            for (int i = 0; i < 32; ++i)
                acc = fmaf(Atemp[row * 32 + i], Wns[i * 32 + col], acc);
            LR[row * 64 + col] = acc;
        }
    }
    __syncthreads();

    float acc[2][2][4];
    #pragma unroll
    for (int mt = 0; mt < 2; ++mt)
        #pragma unroll
        for (int nt = 0; nt < 2; ++nt)
            #pragma unroll
            for (int e = 0; e < 4; ++e) acc[mt][nt][e] = 0.f;

    int m0w = (wid >> 1) * 32, n0w = (wid & 1) * 16;
    int li = lane & 7, lt = lane >> 3;
    int rA_off = li + ((lt & 1) << 3);
    int segA_h = lt >> 1;
    int hB = lt & 1;
    int lobB = (lt >> 1) * 4096;
    int halfc = tid >> 8, ec = tid & 255;

    for (int s = 0; s < 17; ++s) {
        #pragma unroll
        for (int it = 0; it < 16; ++it) {
            int p = it * 512 + tid;
            int row = p >> 5, t0 = (p & 31) * 2;
            const float* LRs = LR + (row >> 7) * 8192;
            int lrow = row & 127;
            float f0, f1;
            if (s == 0) {
                float2 lv = *(const float2*)&LRs[lrow * 64 + t0];
                f0 = lv.x; f1 = lv.y;
            } else {
                int i = 2 * (s - 1) + (t0 >> 5), j = t0 & 31;
                float Lv = LRs[lrow * 64 + i];
                float2 rv = *(const float2*)&LRs[lrow * 64 + 32 + j];
                f0 = Lv * rv.x;
                f1 = Lv * rv.y;
            }
            uint32_t hp, lp;
            split2(f0, f1, hp, lp);
            uint32_t off = row * 128 + ((((t0 >> 3) ^ (row & 7))) << 4) + (t0 & 7) * 2;
            *(uint32_t*)(sm + LA_AHI + off) = hp;
            *(uint32_t*)(sm + LA_ALO + off) = lp;
        }
        cpa_wait<1>();
        __syncthreads();

        if (s + 2 < 17) {
            cpa16(sb + LA_B + ((s + 2) % 3) * 8192 + halfc * 4096 + ec * 16,
                  (halfc ? (const char*)g_walo : (const char*)g_wahi) + (size_t)(s + 2) * 4096 + ec * 16);
        }
        cpa_commit();

        uint32_t Bb = sb + LA_B + (s % 3) * 8192;
        #pragma unroll
        for (int ks = 0; ks < 4; ++ks) {
            uint32_t bf[2][4];
            #pragma unroll
            for (int nt = 0; nt < 2; ++nt) {
                int row = n0w + nt * 8 + li;
                uint32_t addr = Bb + lobB + row * 128 + ((((2 * ks + hB) ^ (row & 7))) << 4);
                ldsm4(bf[nt], addr);
            }
            #pragma unroll
            for (int mt = 0; mt < 2; ++mt) {
                int row = m0w + mt * 16 + rA_off;
                int seg = 2 * ks + segA_h;
                uint32_t addr = sb + LA_AHI + row * 128 + (((seg ^ (row & 7))) << 4);
                uint32_t ah[4], al[4];
                ldsm4(ah, addr);
                ldsm4(al, addr + 32768);
                #pragma unroll
                for (int nt = 0; nt < 2; ++nt) {
                    mma_bf16(acc[mt][nt], ah, bf[nt]);
                    mma_bf16(acc[mt][nt], ah, bf[nt] + 2);
                    mma_bf16(acc[mt][nt], al, bf[nt]);
                }
            }
        }
        __syncthreads();
    }

    const float* bas = (const float*)(sm + LA_BA);
    int q = lane >> 2, c2 = (lane & 3) * 2;
    #pragma unroll
    for (int mt = 0; mt < 2; ++mt) {
        #pragma unroll
        for (int nt = 0; nt < 2; ++nt) {
            int col = n0w + nt * 8 + c2;
            float bax = bas[col], bay = bas[col + 1];
            int gr0 = m0w + mt * 16 + q;
            int gr1 = gr0 + 8;
            float* d = acc[mt][nt];
            size_t o0 = (size_t)(n0 + (gr0 & 127)) * 64 + (gr0 >> 7) * 32 + col;
            size_t o1 = (size_t)(n0 + (gr1 & 127)) * 64 + (gr1 >> 7) * 32 + col;
            g_lr[o0]     = d[0] + bax;
            g_lr[o0 + 1] = d[1] + bay;
            g_lr[o1]     = d[2] + bax;
            g_lr[o1 + 1] = d[3] + bay;
        }
    }
}

// =====================================================================
// Kernel B v2: factored bilinear MMA with register-resident R.
// D = [L|R]@W0 + sum_i diag(L_i) * (R @ Q_i).
// Only chunk 0 is materialized; bilinear terms reuse R fragments.
// =====================================================================
#define SM_LR   0             // float[128*64]                    32768
#define SM_AHI  32768         // bf16[128][64] swizzled           16384
#define SM_ALO  49152         // bf16[128][64] swizzled           16384
#define SM_B    65536         // 3 x (hi 16384 + lo 16384)        98304
#define SM_LT   163840        // float[32][132]                   16896
#define SM_BS1  180736        // float[128]
#define SM_W2   181248        // float[128]
#define SM_DS   181760        // float[128][4]
#define KM_SMEM 183808

__global__ __launch_bounds__(512, 1) void k_main(
    const float* __restrict__ bs1, const float* __restrict__ Ws2,
    const float* __restrict__ bs2, float* __restrict__ out)
{
    extern __shared__ __align__(16) char sm[];
    float* LR = (float*)(sm + SM_LR);
    float* LT = (float*)(sm + SM_LT);            // LT[i][row], stride 132
    uint32_t sb = s2u(sm);
    int tid = threadIdx.x;
    int wid = tid >> 5, lane = tid & 31;
    int n0 = blockIdx.x << 7;

    // prefetch B chunks 0,1
    #pragma unroll
    for (int p = 0; p < 2; ++p) {
        #pragma unroll
        for (int qq = 0; qq < 2; ++qq) {
            int e = qq * 512 + tid;
            cpa16(sb + SM_B + p * 32768 + e * 16,         (const char*)g_whi + (size_t)p * 16384 + e * 16);
            cpa16(sb + SM_B + p * 32768 + 16384 + e * 16, (const char*)g_wlo + (size_t)p * 16384 + e * 16);
        }
        cpa_commit();
    }

    // load LR rows; also build LT (transposed L) for the scaling reads
    #pragma unroll
    for (int it = 0; it < 4; ++it) {
        int e4 = it * 512 + tid;
        int r = e4 >> 4, qq = e4 & 15;
        float4 v = *(const float4*)&g_lr[(size_t)(n0 + r) * 64 + qq * 4];
        *(float4*)&LR[r * 64 + qq * 4] = v;
        if (qq < 8) {
            int k0 = qq * 4;
            LT[(k0 + 0) * 132 + r] = v.x;
            LT[(k0 + 1) * 132 + r] = v.y;
            LT[(k0 + 2) * 132 + r] = v.z;
            LT[(k0 + 3) * 132 + r] = v.w;
        }
    }
    if (tid < 128) {
        ((float*)(sm + SM_BS1))[tid] = bs1[tid];
        ((float*)(sm + SM_W2))[tid]  = Ws2[tid];
    }
    __syncthreads();

    // materialize A0 = split([L|R]) once
    #pragma unroll
    for (int it = 0; it < 8; ++it) {
        int p = it * 512 + tid;
        int row = p >> 5, t0 = (p & 31) * 2;
        float2 lv = *(const float2*)&LR[row * 64 + t0];
        uint32_t hp, lp;
        split2(lv.x, lv.y, hp, lp);
        uint32_t off = row * 128 + ((((t0 >> 3) ^ (row & 7))) << 4) + (t0 & 7) * 2;
        *(uint32_t*)(sm + SM_AHI + off) = hp;
        *(uint32_t*)(sm + SM_ALO + off) = lp;
    }
    cpa_wait<1>();
    __syncthreads();                             // A0 + B chunk 0 visible

    // prefetch chunk 2 into ring slot 2
    #pragma unroll
    for (int qq = 0; qq < 2; ++qq) {
        int e = qq * 512 + tid;
        cpa16(sb + SM_B + 2 * 32768 + e * 16,         (const char*)g_whi + (size_t)2 * 16384 + e * 16);
        cpa16(sb + SM_B + 2 * 32768 + 16384 + e * 16, (const char*)g_wlo + (size_t)2 * 16384 + e * 16);
    }
    cpa_commit();

    float acc[2][4][4];
    #pragma unroll
    for (int mt = 0; mt < 2; ++mt)
        #pragma unroll
        for (int nt = 0; nt < 4; ++nt)
            #pragma unroll
            for (int e = 0; e < 4; ++e) acc[mt][nt][e] = 0.f;

    int m0w = (wid >> 2) * 32, n0w = (wid & 3) * 32;
    int li = lane & 7, lt = lane >> 3;
    int rA_off = li + ((lt & 1) << 3);
    int segA_h = lt >> 1;
    int hB = lt & 1;
    int lobB = (lt >> 1) * 16384;
    int ql = lane >> 2;                          // accumulator row-within-8

    // base term (chunk 0): [L|R] @ W0 — save R fragments (ks=2,3) in regs
    uint32_t rfh[2][2][4], rfl[2][2][4];
    {
        uint32_t Bb = sb + SM_B;                 // slot 0
        #pragma unroll
        for (int ks = 0; ks < 4; ++ks) {
            uint32_t bf[4][4];
            #pragma unroll
            for (int nt = 0; nt < 4; ++nt) {
                int row = n0w + nt * 8 + li;
                uint32_t addr = Bb + lobB + row * 128 + ((((2 * ks + hB) ^ (row & 7))) << 4);
                ldsm4(bf[nt], addr);
            }
            #pragma unroll
            for (int mt = 0; mt < 2; ++mt) {
                int row = m0w + mt * 16 + rA_off;
                int seg = 2 * ks + segA_h;
                uint32_t addr = sb + SM_AHI + row * 128 + (((seg ^ (row & 7))) << 4);
                uint32_t ah[4], al[4];
                ldsm4(ah, addr);
                ldsm4(al, addr + 16384);
                if (ks >= 2) {
                    #pragma unroll
                    for (int e = 0; e < 4; ++e) {
                        rfh[mt][ks - 2][e] = ah[e];
                        rfl[mt][ks - 2][e] = al[e];
                    }
                }
                #pragma unroll
                for (int nt = 0; nt < 4; ++nt) {
                    mma_bf16(acc[mt][nt], ah, bf[nt]);
                    mma_bf16(acc[mt][nt], ah, bf[nt] + 2);
                    mma_bf16(acc[mt][nt], al, bf[nt]);
                }
            }
        }
    }

    // bilinear terms: chunks 1..16 hold Q_{2(s-1)} (segs 0-3) and Q_{2(s-1)+1} (segs 4-7)
    for (int s = 1; s < 17; ++s) {
        cpa_wait<1>();
        __syncthreads();                         // B chunk s visible; slot (s+2)%3 free
        if (s + 2 < 17) {
            #pragma unroll
            for (int qq = 0; qq < 2; ++qq) {
                int e = qq * 512 + tid;
                cpa16(sb + SM_B + ((s + 2) % 3) * 32768 + e * 16,
                      (const char*)g_whi + (size_t)(s + 2) * 16384 + e * 16);
                cpa16(sb + SM_B + ((s + 2) % 3) * 32768 + 16384 + e * 16,
                      (const char*)g_wlo + (size_t)(s + 2) * 16384 + e * 16);
            }
        }
        cpa_commit();

        uint32_t Bb = sb + SM_B + (s % 3) * 32768;
        #pragma unroll
        for (int h = 0; h < 2; ++h) {
            int i = 2 * (s - 1) + h;
            uint32_t bf[4][2][4];                // [nt][k2][folded hi/lo]
            #pragma unroll
            for (int nt = 0; nt < 4; ++nt) {
                #pragma unroll
                for (int k2 = 0; k2 < 2; ++k2) {
                    int row = n0w + nt * 8 + li;
                    uint32_t addr = Bb + lobB + row * 128
                                  + ((((4 * h + 2 * k2 + hB) ^ (row & 7))) << 4);
                    ldsm4(bf[nt][k2], addr);
                }
            }
            #pragma unroll
            for (int mt = 0; mt < 2; ++mt) {
                float l0 = LT[i * 132 + m0w + mt * 16 + ql];
                float l1 = LT[i * 132 + m0w + mt * 16 + ql + 8];
                #pragma unroll
                for (int nt = 0; nt < 4; ++nt) {
                    float P[4];
                    mma_bf16_c0(P, rfh[mt][0], bf[nt][0]);       // hi*hi k2=0
                    mma_bf16(P, rfh[mt][0], bf[nt][0] + 2);      // hi*lo
                    mma_bf16(P, rfl[mt][0], bf[nt][0]);          // lo*hi
                    mma_bf16(P, rfh[mt][1], bf[nt][1]);          // k2=1
                    mma_bf16(P, rfh[mt][1], bf[nt][1] + 2);
                    mma_bf16(P, rfl[mt][1], bf[nt][1]);
                    acc[mt][nt][0] = fmaf(l0, P[0], acc[mt][nt][0]);
                    acc[mt][nt][1] = fmaf(l0, P[1], acc[mt][nt][1]);
                    acc[mt][nt][2] = fmaf(l1, P[2], acc[mt][nt][2]);
                    acc[mt][nt][3] = fmaf(l1, P[3], acc[mt][nt][3]);
                }
            }
        }
    }

    // epilogue: +bs1, elu, dot Ws2, reduce
    const float* bs1s = (const float*)(sm + SM_BS1);
    const float* w2s  = (const float*)(sm + SM_W2);
    float* Dsum = (float*)(sm + SM_DS);
    int c2 = (lane & 3) * 2;
    float bias2 = bs2[0];
    #pragma unroll
    for (int mt = 0; mt < 2; ++mt) {
        float s0 = 0.f, s1 = 0.f;
        #pragma unroll
        for (int nt = 0; nt < 4; ++nt) {
            int col = n0w + nt * 8 + c2;
            float2 bv = *(const float2*)&bs1s[col];
            float2 wv = *(const float2*)&w2s[col];
            float* d = acc[mt][nt];
            float x0 = d[0] + bv.x, x1 = d[1] + bv.y;
            float x2 = d[2] + bv.x, x3 = d[3] + bv.y;
            float h0 = x0 > 0.f ? x0 : expm1f(x0);
            float h1 = x1 > 0.f ? x1 : expm1f(x1);
            float h2 = x2 > 0.f ? x2 : expm1f(x2);
            float h3 = x3 > 0.f ? x3 : expm1f(x3);
            s0 = fmaf(h0, wv.x, fmaf(h1, wv.y, s0));
            s1 = fmaf(h2, wv.x, fmaf(h3, wv.y, s1));
        }
        s0 += __shfl_xor_sync(0xffffffffu, s0, 1);
        s0 += __shfl_xor_sync(0xffffffffu, s0, 2);
        s1 += __shfl_xor_sync(0xffffffffu, s1, 1);
        s1 += __shfl_xor_sync(0xffffffffu, s1, 2);
        if ((lane & 3) == 0) {
            int row = m0w + mt * 16 + ql;
            Dsum[row * 4 + (wid & 3)] = s0;
            Dsum[(row + 8) * 4 + (wid & 3)] = s1;
        }
    }
    __syncthreads();
    if (tid < 128) {
        float v = Dsum[tid * 4] + Dsum[tid * 4 + 1] + Dsum[tid * 4 + 2] + Dsum[tid * 4 + 3];
        out[n0 + tid] = v + bias2;
    }
}

extern "C" void kernel_launch(void* const* d_in, const int* in_sizes, int n_in,
                              void* d_out, int out_size)
{
    const float* concepts = (const float*)d_in[0];
    const float* Wn  = (const float*)d_in[1];
    const float* bn  = (const float*)d_in[2];
    const float* Wa  = (const float*)d_in[3];
    const float* ba  = (const float*)d_in[4];
    const float* Ws1 = (const float*)d_in[5];
    const float* bs1 = (const float*)d_in[6];
    const float* Ws2 = (const float*)d_in[7];
    const float* bs2 = (const float*)d_in[8];
    const void*  idx = d_in[9];
    int nrows = in_sizes[9] / 4;

    static int inited = 0;
    if (!inited) {
        cudaFuncSetAttribute(k_main, cudaFuncAttributeMaxDynamicSharedMemorySize, KM_SMEM);
        cudaFuncSetAttribute(k_lrm,  cudaFuncAttributeMaxDynamicSharedMemorySize, LA_SMEM);
        inited = 1;
    }

    k_conv<<<(17 * 64 * 128 + 255) / 256, 256>>>(Ws1);
    k_conv_a<<<(17 * 64 * 32 + 255) / 256, 256>>>(Wa);
    k_lrm<<<nrows / 128, 512, LA_SMEM>>>(concepts, Wn, bn, ba, idx);
    k_main<<<nrows / 128, 512, KM_SMEM>>>(bs1, Ws2, bs2, (float*)d_out);
}

// round 15
// speedup vs baseline: 1.2793x; 1.2137x over previous
#include <cuda_runtime.h>
#include <cuda_bf16.h>
#include <cstdint>

#define NROWS_MAX 65536
typedef unsigned long long ull;

// scratch: left/right activations [n][0..31]=left, [n][32..63]=right
__device__ __align__(16) float g_lr[(size_t)NROWS_MAX * 64];
// pre-split Ws1, bf16, N-major, XOR-swizzled: [17 chunks][128 n][64 k]
__device__ __align__(16) __nv_bfloat16 g_whi[17 * 8192];
__device__ __align__(16) __nv_bfloat16 g_wlo[17 * 8192];
// pre-split Wa, bf16, N-major, XOR-swizzled: [17 chunks][32 n][64 k]
__device__ __align__(16) __nv_bfloat16 g_wahi[17 * 2048];
__device__ __align__(16) __nv_bfloat16 g_walo[17 * 2048];

// ---------- cp.async ----------
__device__ __forceinline__ uint32_t s2u(const void* p) {
    uint32_t a;
    asm("{ .reg .u64 t; cvta.to.shared.u64 t, %1; cvt.u32.u64 %0, t; }" : "=r"(a) : "l"(p));
    return a;
}
__device__ __forceinline__ void cpa16(uint32_t dst, const void* src) {
    asm volatile("cp.async.ca.shared.global [%0], [%1], 16;" :: "r"(dst), "l"(src));
}
__device__ __forceinline__ void cpa_commit() { asm volatile("cp.async.commit_group;"); }
template<int N> __device__ __forceinline__ void cpa_wait() {
    asm volatile("cp.async.wait_group %0;" :: "n"(N));
}
// ---------- tensor primitives ----------
__device__ __forceinline__ void ldsm4(uint32_t* r, uint32_t a) {
    asm volatile("ldmatrix.sync.aligned.m8n8.x4.shared.b16 {%0,%1,%2,%3}, [%4];"
        : "=r"(r[0]), "=r"(r[1]), "=r"(r[2]), "=r"(r[3]) : "r"(a));
}
__device__ __forceinline__ void mma_bf16(float* d, const uint32_t* a, const uint32_t* b) {
    asm volatile("mma.sync.aligned.m16n8k16.row.col.f32.bf16.bf16.f32 "
        "{%0,%1,%2,%3}, {%4,%5,%6,%7}, {%8,%9}, {%0,%1,%2,%3};"
        : "+f"(d[0]), "+f"(d[1]), "+f"(d[2]), "+f"(d[3])
        : "r"(a[0]), "r"(a[1]), "r"(a[2]), "r"(a[3]), "r"(b[0]), "r"(b[1]));
}
__device__ __forceinline__ void mma_bf16_c0(float* d, const uint32_t* a, const uint32_t* b) {
    asm volatile("mma.sync.aligned.m16n8k16.row.col.f32.bf16.bf16.f32 "
        "{%0,%1,%2,%3}, {%4,%5,%6,%7}, {%8,%9}, {%10,%11,%12,%13};"
        : "=f"(d[0]), "=f"(d[1]), "=f"(d[2]), "=f"(d[3])
        : "r"(a[0]), "r"(a[1]), "r"(a[2]), "r"(a[3]), "r"(b[0]), "r"(b[1]),
          "f"(0.f), "f"(0.f), "f"(0.f), "f"(0.f));
}
// split a pair of floats into packed bf16 hi / lo
__device__ __forceinline__ void split2(float f0, float f1, uint32_t& hp, uint32_t& lp) {
    asm("cvt.rn.bf16x2.f32 %0, %1, %2;" : "=r"(hp) : "f"(f1), "f"(f0));
    float b0 = __uint_as_float(hp << 16);
    float b1 = __uint_as_float(hp & 0xffff0000u);
    asm("cvt.rn.bf16x2.f32 %0, %1, %2;" : "=r"(lp) : "f"(f1 - b1), "f"(f0 - b0));
}

// =====================================================================
// Converters: split weights -> bf16 hi/lo, N-major swizzled
// =====================================================================
__global__ void k_conv(const float* __restrict__ Ws1) {
    int gid = blockIdx.x * 256 + threadIdx.x;
    if (gid >= 17 * 64 * 128) return;
    int s = gid >> 13, rem = gid & 8191;
    int k = rem >> 7, n = rem & 127;
    float w = Ws1[(s * 64 + k) * 128 + n];
    __nv_bfloat16 hi = __float2bfloat16(w);
    __nv_bfloat16 lo = __float2bfloat16(w - __bfloat162float(hi));
    uint32_t off = (uint32_t)s * 16384 + n * 128 + ((((k >> 3) ^ (n & 7))) << 4) + (k & 7) * 2;
    *(__nv_bfloat16*)((char*)g_whi + off) = hi;
    *(__nv_bfloat16*)((char*)g_wlo + off) = lo;
}
__global__ void k_conv_a(const float* __restrict__ Wa) {
    int gid = blockIdx.x * 256 + threadIdx.x;
    if (gid >= 17 * 64 * 32) return;
    int s = gid >> 11, rem = gid & 2047;
    int k = rem >> 5, n = rem & 31;
    float w = Wa[(s * 64 + k) * 32 + n];
    __nv_bfloat16 hi = __float2bfloat16(w);
    __nv_bfloat16 lo = __float2bfloat16(w - __bfloat162float(hi));
    uint32_t off = (uint32_t)s * 4096 + n * 128 + ((((k >> 3) ^ (n & 7))) << 4) + (k & 7) * 2;
    *(__nv_bfloat16*)((char*)g_wahi + off) = hi;
    *(__nv_bfloat16*)((char*)g_walo + off) = lo;
}

// =====================================================================
// Kernel A v2: factored bilinear MMA with register-resident v.
// F@Wa = [u|v]@W0a + sum_i diag(u_i)*(v @ Qa_i)
// M=256 stacked (left rows 0-127 u=na,v=b; right 128-255 u=c,v=d).
// 512 threads; warp grid 8M x 2N; warp tile 32x16.
// =====================================================================
#define LB_LR    0            // float[2][128][64]               65536
#define LB_AHI   65536        // bf16[256][64] swizzled          32768 (Atemp overlay pre-split)
#define LB_ALO   98304        // bf16[256][64] swizzled          32768
#define LB_B     131072       // 3 x (hi 4096 + lo 4096)         24576
#define LB_UT    155648       // float[32][257]                  32896
#define LB_WN    188544       // float[32][32]                    4096
#define LB_BN    192640       // float[32]
#define LB_BA    192768       // float[32]
#define LB_SMEM  192896

__global__ __launch_bounds__(512, 1) void k_lrm(
    const float* __restrict__ concepts, const float* __restrict__ Wn,
    const float* __restrict__ bn, const float* __restrict__ ba,
    const void* __restrict__ idxp)
{
    extern __shared__ __align__(16) char sm[];
    float* LR = (float*)(sm + LB_LR);
    float* UT = (float*)(sm + LB_UT);
    uint32_t sb = s2u(sm);
    int tid = threadIdx.x;
    int wid = tid >> 5, lane = tid & 31;
    int n0 = blockIdx.x << 7;
    int halfc = tid >> 8, ec = tid & 255;       // B-copy lane

    // prefetch B chunks 0,1 (8KB each = hi 4KB + lo 4KB)
    #pragma unroll
    for (int p = 0; p < 2; ++p) {
        cpa16(sb + LB_B + p * 8192 + halfc * 4096 + ec * 16,
              (halfc ? (const char*)g_walo : (const char*)g_wahi) + (size_t)p * 4096 + ec * 16);
        cpa_commit();
    }

    // load Wn, bn, ba
    {
        float* Wns = (float*)(sm + LB_WN);
        for (int e = tid; e < 1024; e += 512) Wns[e] = Wn[e];
        if (tid < 32) {
            ((float*)(sm + LB_BN))[tid] = bn[tid];
            ((float*)(sm + LB_BA))[tid] = ba[tid];
        }
    }

    const int* idx32 = (const int*)idxp;
    bool is64 = (idx32[1] == 0) & (idx32[3] == 0) & (idx32[5] == 0) & (idx32[7] == 0);
    const long long* idx64 = (const long long*)idxp;

    // gather: a -> Atemp; b -> LR1[.,32+]; c -> LR2[.,0+] & UT[.,128+]; d -> LR2[.,32+]
    float* Atemp = (float*)(sm + LB_AHI);       // overlay, consumed before A0 split
    for (int e = tid; e < 4096; e += 512) {
        int row = e >> 5, col = e & 31;
        long long base = (long long)(n0 + row) * 4;
        long long ia = is64 ? idx64[base]     : (long long)idx32[base];
        long long ib = is64 ? idx64[base + 1] : (long long)idx32[base + 1];
        long long ic = is64 ? idx64[base + 2] : (long long)idx32[base + 2];
        long long id = is64 ? idx64[base + 3] : (long long)idx32[base + 3];
        float av = concepts[ia * 32 + col];
        float bv = concepts[ib * 32 + col];
        float cv = concepts[ic * 32 + col];
        float dv = concepts[id * 32 + col];
        Atemp[row * 32 + col]          = av;
        LR[row * 64 + 32 + col]        = bv;
        LR[8192 + row * 64 + col]      = cv;
        LR[8192 + row * 64 + 32 + col] = dv;
        UT[col * 257 + 128 + row]      = cv;
    }
    __syncthreads();

    // na = a @ Wn + bn -> LR1[.,0..31] and UT[.,0..127]
    {
        const float* Wns = (const float*)(sm + LB_WN);
        const float* bns = (const float*)(sm + LB_BN);
        for (int e = tid; e < 4096; e += 512) {
            int row = e >> 5, col = e & 31;
            float acc = bns[col];
            #pragma unroll
            for (int i = 0; i < 32; ++i)
                acc = fmaf(Atemp[row * 32 + i], Wns[i * 32 + col], acc);
            LR[row * 64 + col] = acc;
            UT[col * 257 + row] = acc;
        }
    }
    __syncthreads();    // Atemp consumed; A region reusable

    // materialize A0 = split([u|v]) for all 256 stacked rows (once)
    #pragma unroll
    for (int it = 0; it < 16; ++it) {
        int p = it * 512 + tid;
        int row = p >> 5, t0 = (p & 31) * 2;
        const float* LRs = LR + (row >> 7) * 8192;
        int lrow = row & 127;
        float2 lv = *(const float2*)&LRs[lrow * 64 + t0];
        uint32_t hp, lp;
        split2(lv.x, lv.y, hp, lp);
        uint32_t off = row * 128 + ((((t0 >> 3) ^ (row & 7))) << 4) + (t0 & 7) * 2;
        *(uint32_t*)(sm + LB_AHI + off) = hp;
        *(uint32_t*)(sm + LB_ALO + off) = lp;
    }
    cpa_wait<1>();
    __syncthreads();                            // A0 + B chunk 0 visible

    // prefetch chunk 2 into ring slot 2
    cpa16(sb + LB_B + 2 * 8192 + halfc * 4096 + ec * 16,
          (halfc ? (const char*)g_walo : (const char*)g_wahi) + (size_t)2 * 4096 + ec * 16);
    cpa_commit();

    float acc[2][2][4];
    #pragma unroll
    for (int mt = 0; mt < 2; ++mt)
        #pragma unroll
        for (int nt = 0; nt < 2; ++nt)
            #pragma unroll
            for (int e = 0; e < 4; ++e) acc[mt][nt][e] = 0.f;

    int m0w = (wid >> 1) * 32, n0w = (wid & 1) * 16;
    int li = lane & 7, lt = lane >> 3;
    int rA_off = li + ((lt & 1) << 3);
    int segA_h = lt >> 1;
    int hB = lt & 1;
    int lobB = (lt >> 1) * 4096;
    int ql = lane >> 2;

    // base term (chunk 0): [u|v] @ W0a — save v fragments (ks=2,3)
    uint32_t rfh[2][2][4], rfl[2][2][4];
    {
        uint32_t Bb = sb + LB_B;                 // slot 0
        #pragma unroll
        for (int ks = 0; ks < 4; ++ks) {
            uint32_t bf[2][4];
            #pragma unroll
            for (int nt = 0; nt < 2; ++nt) {
                int row = n0w + nt * 8 + li;
                uint32_t addr = Bb + lobB + row * 128 + ((((2 * ks + hB) ^ (row & 7))) << 4);
                ldsm4(bf[nt], addr);
            }
            #pragma unroll
            for (int mt = 0; mt < 2; ++mt) {
                int row = m0w + mt * 16 + rA_off;
                int seg = 2 * ks + segA_h;
                uint32_t addr = sb + LB_AHI + row * 128 + (((seg ^ (row & 7))) << 4);
                uint32_t ah[4], al[4];
                ldsm4(ah, addr);
                ldsm4(al, addr + 32768);
                if (ks >= 2) {
                    #pragma unroll
                    for (int e = 0; e < 4; ++e) {
                        rfh[mt][ks - 2][e] = ah[e];
                        rfl[mt][ks - 2][e] = al[e];
                    }
                }
                #pragma unroll
                for (int nt = 0; nt < 2; ++nt) {
                    mma_bf16(acc[mt][nt], ah, bf[nt]);
                    mma_bf16(acc[mt][nt], ah, bf[nt] + 2);
                    mma_bf16(acc[mt][nt], al, bf[nt]);
                }
            }
        }
    }

    // bilinear terms: chunks 1..16, each holds Q_{2(s-1)} (segs 0-3) + Q_{2(s-1)+1} (segs 4-7)
    for (int s = 1; s < 17; ++s) {
        cpa_wait<1>();
        __syncthreads();
        if (s + 2 < 17) {
            cpa16(sb + LB_B + ((s + 2) % 3) * 8192 + halfc * 4096 + ec * 16,
                  (halfc ? (const char*)g_walo : (const char*)g_wahi) + (size_t)(s + 2) * 4096 + ec * 16);
        }
        cpa_commit();

        uint32_t Bb = sb + LB_B + (s % 3) * 8192;
        #pragma unroll
        for (int h = 0; h < 2; ++h) {
            int i = 2 * (s - 1) + h;
            uint32_t bf[2][2][4];                // [nt][k2][folded hi/lo]
            #pragma unroll
            for (int nt = 0; nt < 2; ++nt) {
                #pragma unroll
                for (int k2 = 0; k2 < 2; ++k2) {
                    int row = n0w + nt * 8 + li;
                    uint32_t addr = Bb + lobB + row * 128
                                  + ((((4 * h + 2 * k2 + hB) ^ (row & 7))) << 4);
                    ldsm4(bf[nt][k2], addr);
                }
            }
            #pragma unroll
            for (int mt = 0; mt < 2; ++mt) {
                float l0 = UT[i * 257 + m0w + mt * 16 + ql];
                float l1 = UT[i * 257 + m0w + mt * 16 + ql + 8];
                #pragma unroll
                for (int nt = 0; nt < 2; ++nt) {
                    float P[4];
                    mma_bf16_c0(P, rfh[mt][0], bf[nt][0]);
                    mma_bf16(P, rfh[mt][0], bf[nt][0] + 2);
                    mma_bf16(P, rfl[mt][0], bf[nt][0]);
                    mma_bf16(P, rfh[mt][1], bf[nt][1]);
                    mma_bf16(P, rfh[mt][1], bf[nt][1] + 2);
                    mma_bf16(P, rfl[mt][1], bf[nt][1]);
                    acc[mt][nt][0] = fmaf(l0, P[0], acc[mt][nt][0]);
                    acc[mt][nt][1] = fmaf(l0, P[1], acc[mt][nt][1]);
                    acc[mt][nt][2] = fmaf(l1, P[2], acc[mt][nt][2]);
                    acc[mt][nt][3] = fmaf(l1, P[3], acc[mt][nt][3]);
                }
            }
        }
    }

    // epilogue: +ba, write g_lr (rows 0-127 -> left half, 128-255 -> right half)
    const float* bas = (const float*)(sm + LB_BA);
    int c2 = (lane & 3) * 2;
    #pragma unroll
    for (int mt = 0; mt < 2; ++mt) {
        #pragma unroll
        for (int nt = 0; nt < 2; ++nt) {
            int col = n0w + nt * 8 + c2;
            float bax = bas[col], bay = bas[col + 1];
            int gr0 = m0w + mt * 16 + ql;
            int gr1 = gr0 + 8;
            float* d = acc[mt][nt];
            size_t o0 = (size_t)(n0 + (gr0 & 127)) * 64 + (gr0 >> 7) * 32 + col;
            size_t o1 = (size_t)(n0 + (gr1 & 127)) * 64 + (gr1 >> 7) * 32 + col;
            g_lr[o0]     = d[0] + bax;
            g_lr[o0 + 1] = d[1] + bay;
            g_lr[o1]     = d[2] + bax;
            g_lr[o1 + 1] = d[3] + bay;
        }
    }
}

// =====================================================================
// Kernel B v2: factored bilinear MMA with register-resident R.
// (R13 proven form, unchanged.)
// =====================================================================
#define SM_LR   0             // float[128*64]                    32768
#define SM_AHI  32768         // bf16[128][64] swizzled           16384
#define SM_ALO  49152         // bf16[128][64] swizzled           16384
#define SM_B    65536         // 3 x (hi 16384 + lo 16384)        98304
#define SM_LT   163840        // float[32][132]                   16896
#define SM_BS1  180736        // float[128]
#define SM_W2   181248        // float[128]
#define SM_DS   181760        // float[128][4]
#define KM_SMEM 183808

__global__ __launch_bounds__(512, 1) void k_main(
    const float* __restrict__ bs1, const float* __restrict__ Ws2,
    const float* __restrict__ bs2, float* __restrict__ out)
{
    extern __shared__ __align__(16) char sm[];
    float* LR = (float*)(sm + SM_LR);
    float* LT = (float*)(sm + SM_LT);
    uint32_t sb = s2u(sm);
    int tid = threadIdx.x;
    int wid = tid >> 5, lane = tid & 31;
    int n0 = blockIdx.x << 7;

    #pragma unroll
    for (int p = 0; p < 2; ++p) {
        #pragma unroll
        for (int qq = 0; qq < 2; ++qq) {
            int e = qq * 512 + tid;
            cpa16(sb + SM_B + p * 32768 + e * 16,         (const char*)g_whi + (size_t)p * 16384 + e * 16);
            cpa16(sb + SM_B + p * 32768 + 16384 + e * 16, (const char*)g_wlo + (size_t)p * 16384 + e * 16);
        }
        cpa_commit();
    }

    #pragma unroll
    for (int it = 0; it < 4; ++it) {
        int e4 = it * 512 + tid;
        int r = e4 >> 4, qq = e4 & 15;
        float4 v = *(const float4*)&g_lr[(size_t)(n0 + r) * 64 + qq * 4];
        *(float4*)&LR[r * 64 + qq * 4] = v;
        if (qq < 8) {
            int k0 = qq * 4;
            LT[(k0 + 0) * 132 + r] = v.x;
            LT[(k0 + 1) * 132 + r] = v.y;
            LT[(k0 + 2) * 132 + r] = v.z;
            LT[(k0 + 3) * 132 + r] = v.w;
        }
    }
    if (tid < 128) {
        ((float*)(sm + SM_BS1))[tid] = bs1[tid];
        ((float*)(sm + SM_W2))[tid]  = Ws2[tid];
    }
    __syncthreads();

    #pragma unroll
    for (int it = 0; it < 8; ++it) {
        int p = it * 512 + tid;
        int row = p >> 5, t0 = (p & 31) * 2;
        float2 lv = *(const float2*)&LR[row * 64 + t0];
        uint32_t hp, lp;
        split2(lv.x, lv.y, hp, lp);
        uint32_t off = row * 128 + ((((t0 >> 3) ^ (row & 7))) << 4) + (t0 & 7) * 2;
        *(uint32_t*)(sm + SM_AHI + off) = hp;
        *(uint32_t*)(sm + SM_ALO + off) = lp;
    }
    cpa_wait<1>();
    __syncthreads();

    #pragma unroll
    for (int qq = 0; qq < 2; ++qq) {
        int e = qq * 512 + tid;
        cpa16(sb + SM_B + 2 * 32768 + e * 16,         (const char*)g_whi + (size_t)2 * 16384 + e * 16);
        cpa16(sb + SM_B + 2 * 32768 + 16384 + e * 16, (const char*)g_wlo + (size_t)2 * 16384 + e * 16);
    }
    cpa_commit();

    float acc[2][4][4];
    #pragma unroll
    for (int mt = 0; mt < 2; ++mt)
        #pragma unroll
        for (int nt = 0; nt < 4; ++nt)
            #pragma unroll
            for (int e = 0; e < 4; ++e) acc[mt][nt][e] = 0.f;

    int m0w = (wid >> 2) * 32, n0w = (wid & 3) * 32;
    int li = lane & 7, lt = lane >> 3;
    int rA_off = li + ((lt & 1) << 3);
    int segA_h = lt >> 1;
    int hB = lt & 1;
    int lobB = (lt >> 1) * 16384;
    int ql = lane >> 2;

    uint32_t rfh[2][2][4], rfl[2][2][4];
    {
        uint32_t Bb = sb + SM_B;
        #pragma unroll
        for (int ks = 0; ks < 4; ++ks) {
            uint32_t bf[4][4];
            #pragma unroll
            for (int nt = 0; nt < 4; ++nt) {
                int row = n0w + nt * 8 + li;
                uint32_t addr = Bb + lobB + row * 128 + ((((2 * ks + hB) ^ (row & 7))) << 4);
                ldsm4(bf[nt], addr);
            }
            #pragma unroll
            for (int mt = 0; mt < 2; ++mt) {
                int row = m0w + mt * 16 + rA_off;
                int seg = 2 * ks + segA_h;
                uint32_t addr = sb + SM_AHI + row * 128 + (((seg ^ (row & 7))) << 4);
                uint32_t ah[4], al[4];
                ldsm4(ah, addr);
                ldsm4(al, addr + 16384);
                if (ks >= 2) {
                    #pragma unroll
                    for (int e = 0; e < 4; ++e) {
                        rfh[mt][ks - 2][e] = ah[e];
                        rfl[mt][ks - 2][e] = al[e];
                    }
                }
                #pragma unroll
                for (int nt = 0; nt < 4; ++nt) {
                    mma_bf16(acc[mt][nt], ah, bf[nt]);
                    mma_bf16(acc[mt][nt], ah, bf[nt] + 2);
                    mma_bf16(acc[mt][nt], al, bf[nt]);
                }
            }
        }
    }

    for (int s = 1; s < 17; ++s) {
        cpa_wait<1>();
        __syncthreads();
        if (s + 2 < 17) {
            #pragma unroll
            for (int qq = 0; qq < 2; ++qq) {
                int e = qq * 512 + tid;
                cpa16(sb + SM_B + ((s + 2) % 3) * 32768 + e * 16,
                      (const char*)g_whi + (size_t)(s + 2) * 16384 + e * 16);
                cpa16(sb + SM_B + ((s + 2) % 3) * 32768 + 16384 + e * 16,
                      (const char*)g_wlo + (size_t)(s + 2) * 16384 + e * 16);
            }
        }
        cpa_commit();

        uint32_t Bb = sb + SM_B + (s % 3) * 32768;
        #pragma unroll
        for (int h = 0; h < 2; ++h) {
            int i = 2 * (s - 1) + h;
            uint32_t bf[4][2][4];
            #pragma unroll
            for (int nt = 0; nt < 4; ++nt) {
                #pragma unroll
                for (int k2 = 0; k2 < 2; ++k2) {
                    int row = n0w + nt * 8 + li;
                    uint32_t addr = Bb + lobB + row * 128
                                  + ((((4 * h + 2 * k2 + hB) ^ (row & 7))) << 4);
                    ldsm4(bf[nt][k2], addr);
                }
            }
            #pragma unroll
            for (int mt = 0; mt < 2; ++mt) {
                float l0 = LT[i * 132 + m0w + mt * 16 + ql];
                float l1 = LT[i * 132 + m0w + mt * 16 + ql + 8];
                #pragma unroll
                for (int nt = 0; nt < 4; ++nt) {
                    float P[4];
                    mma_bf16_c0(P, rfh[mt][0], bf[nt][0]);
                    mma_bf16(P, rfh[mt][0], bf[nt][0] + 2);
                    mma_bf16(P, rfl[mt][0], bf[nt][0]);
                    mma_bf16(P, rfh[mt][1], bf[nt][1]);
                    mma_bf16(P, rfh[mt][1], bf[nt][1] + 2);
                    mma_bf16(P, rfl[mt][1], bf[nt][1]);
                    acc[mt][nt][0] = fmaf(l0, P[0], acc[mt][nt][0]);
                    acc[mt][nt][1] = fmaf(l0, P[1], acc[mt][nt][1]);
                    acc[mt][nt][2] = fmaf(l1, P[2], acc[mt][nt][2]);
                    acc[mt][nt][3] = fmaf(l1, P[3], acc[mt][nt][3]);
                }
            }
        }
    }

    const float* bs1s = (const float*)(sm + SM_BS1);
    const float* w2s  = (const float*)(sm + SM_W2);
    float* Dsum = (float*)(sm + SM_DS);
    int c2 = (lane & 3) * 2;
    float bias2 = bs2[0];
    #pragma unroll
    for (int mt = 0; mt < 2; ++mt) {
        float s0 = 0.f, s1 = 0.f;
        #pragma unroll
        for (int nt = 0; nt < 4; ++nt) {
            int col = n0w + nt * 8 + c2;
            float2 bv = *(const float2*)&bs1s[col];
            float2 wv = *(const float2*)&w2s[col];
            float* d = acc[mt][nt];
            float x0 = d[0] + bv.x, x1 = d[1] + bv.y;
            float x2 = d[2] + bv.x, x3 = d[3] + bv.y;
            float h0 = x0 > 0.f ? x0 : expm1f(x0);
            float h1 = x1 > 0.f ? x1 : expm1f(x1);
            float h2 = x2 > 0.f ? x2 : expm1f(x2);
            float h3 = x3 > 0.f ? x3 : expm1f(x3);
            s0 = fmaf(h0, wv.x, fmaf(h1, wv.y, s0));
            s1 = fmaf(h2, wv.x, fmaf(h3, wv.y, s1));
        }
        s0 += __shfl_xor_sync(0xffffffffu, s0, 1);
        s0 += __shfl_xor_sync(0xffffffffu, s0, 2);
        s1 += __shfl_xor_sync(0xffffffffu, s1, 1);
        s1 += __shfl_xor_sync(0xffffffffu, s1, 2);
        if ((lane & 3) == 0) {
            int row = m0w + mt * 16 + ql;
            Dsum[row * 4 + (wid & 3)] = s0;
            Dsum[(row + 8) * 4 + (wid & 3)] = s1;
        }
    }
    __syncthreads();
    if (tid < 128) {
        float v = Dsum[tid * 4] + Dsum[tid * 4 + 1] + Dsum[tid * 4 + 2] + Dsum[tid * 4 + 3];
        out[n0 + tid] = v + bias2;
    }
}

extern "C" void kernel_launch(void* const* d_in, const int* in_sizes, int n_in,
                              void* d_out, int out_size)
{
    const float* concepts = (const float*)d_in[0];
    const float* Wn  = (const float*)d_in[1];
    const float* bn  = (const float*)d_in[2];
    const float* Wa  = (const float*)d_in[3];
    const float* ba  = (const float*)d_in[4];
    const float* Ws1 = (const float*)d_in[5];
    const float* bs1 = (const float*)d_in[6];
    const float* Ws2 = (const float*)d_in[7];
    const float* bs2 = (const float*)d_in[8];
    const void*  idx = d_in[9];
    int nrows = in_sizes[9] / 4;

    static int inited = 0;
    if (!inited) {
        cudaFuncSetAttribute(k_main, cudaFuncAttributeMaxDynamicSharedMemorySize, KM_SMEM);
        cudaFuncSetAttribute(k_lrm,  cudaFuncAttributeMaxDynamicSharedMemorySize, LB_SMEM);
        inited = 1;
    }

    k_conv<<<(17 * 64 * 128 + 255) / 256, 256>>>(Ws1);
    k_conv_a<<<(17 * 64 * 32 + 255) / 256, 256>>>(Wa);
    k_lrm<<<nrows / 128, 512, LB_SMEM>>>(concepts, Wn, bn, ba, idx);
    k_main<<<nrows / 128, 512, KM_SMEM>>>(bs1, Ws2, bs2, (float*)d_out);
}